// round 12
// baseline (speedup 1.0000x reference)
#include <cuda_runtime.h>
#include <cuda_fp16.h>
#include <cstdint>
#include <cstddef>

// B=8, T=1024, C=768, H=12, d=64 — full f16 storage, f32 accumulation.
//   prep:  fused f32 -> f16 convert of x, w_attn, w_proj (one launch)
//   QKV :  m16n8k16 f16 mma, 256 thr / 8 warps (32x64 warp tiles) -> q/k/v f16
//          (odd warps run k-steps reversed to de-phase LDS vs tensor pipes)
//   attn:  f16 flash, 128-query blocks / 8 warps, 64x64 KV tiles double-buffered
//   proj:  same gemm -> out (f32, +bias)

#define ELEMS_BHTD (8 * 12 * 1024 * 64)
#define ELEMS_BTC  (8 * 1024 * 768)
#define N4_X   (ELEMS_BTC / 4)
#define N4_W1  (768 * 2304 / 4)
#define N4_W2  (768 * 768 / 4)

static __device__ __half g_qh[ELEMS_BHTD];
static __device__ __half g_kh[ELEMS_BHTD];
static __device__ __half g_vh[ELEMS_BHTD];
static __device__ __half g_yh[ELEMS_BTC];
static __device__ __half g_xh[ELEMS_BTC];
static __device__ __half g_wh1[768 * 2304];
static __device__ __half g_wh2[768 * 768];

// ---------------------------------------------------------------- helpers --
__device__ __forceinline__ uint32_t smem_u32(const void* p) {
    uint32_t a;
    asm("{ .reg .u64 t; cvta.to.shared.u64 t, %1; cvt.u32.u64 %0, t; }"
        : "=r"(a) : "l"(p));
    return a;
}
__device__ __forceinline__ void cp16(uint32_t s, const void* g) {
    asm volatile("cp.async.ca.shared.global [%0], [%1], 16;"
                 :: "r"(s), "l"(g) : "memory");
}
__device__ __forceinline__ void ldsm4(uint32_t* r, uint32_t a) {
    asm volatile("ldmatrix.sync.aligned.m8n8.x4.shared.b16 {%0,%1,%2,%3}, [%4];"
                 : "=r"(r[0]), "=r"(r[1]), "=r"(r[2]), "=r"(r[3]) : "r"(a));
}
__device__ __forceinline__ void ldsm4t(uint32_t* r, uint32_t a) {
    asm volatile("ldmatrix.sync.aligned.m8n8.x4.trans.shared.b16 {%0,%1,%2,%3}, [%4];"
                 : "=r"(r[0]), "=r"(r[1]), "=r"(r[2]), "=r"(r[3]) : "r"(a));
}
__device__ __forceinline__ void mma_f16(float* c, const uint32_t* a, const uint32_t* b) {
    asm volatile(
        "mma.sync.aligned.m16n8k16.row.col.f32.f16.f16.f32 "
        "{%0,%1,%2,%3}, {%4,%5,%6,%7}, {%8,%9}, {%0,%1,%2,%3};"
        : "+f"(c[0]), "+f"(c[1]), "+f"(c[2]), "+f"(c[3])
        : "r"(a[0]), "r"(a[1]), "r"(a[2]), "r"(a[3]), "r"(b[0]), "r"(b[1]));
}

// ----------------------------------------------------------- fused prep ----
__global__ void __launch_bounds__(256) f2h_all(const float* __restrict__ x,
                                               const float* __restrict__ w1,
                                               const float* __restrict__ w2) {
    int i = blockIdx.x * 256 + threadIdx.x;
    const float* in;
    __half* out;
    if (i < N4_X)                { in = x;  out = g_xh; }
    else if (i < N4_X + N4_W1)   { in = w1; out = g_wh1; i -= N4_X; }
    else if (i < N4_X + N4_W1 + N4_W2) { in = w2; out = g_wh2; i -= N4_X + N4_W1; }
    else return;
    float4 v = ((const float4*)in)[i];
    __half2 h0 = __floats2half2_rn(v.x, v.y);
    __half2 h1 = __floats2half2_rn(v.z, v.w);
    uint2 u;
    u.x = *(uint32_t*)&h0;
    u.y = *(uint32_t*)&h1;
    ((uint2*)out)[i] = u;
}

// ------------------------------------------------------------- f16 GEMM ----
// C[m,n] = A[m,:] . Bw[:,n] (+bias). 128x128 block tile, 256 thr / 8 warps,
// warp tile 32x64 (warp grid 4 rows x 2 cols), BK=64 double-buffered cp.async.
// Odd warps traverse k-steps in reverse to de-phase LDS/tensor usage.
template <int EPI>
__global__ void __launch_bounds__(256, 2) gemm_h(
    const __half* __restrict__ Am, const __half* __restrict__ Bw,
    const float* __restrict__ bias, const float* __restrict__ rel,
    float* __restrict__ Cout, const int N)
{
    constexpr int K = 768;
    constexpr int NC = K / 64;
    constexpr int ASTG = 128 * 72;
    constexpr int BSTG = 64 * 136;

    extern __shared__ __half hsh[];
    __half* As = hsh;                   // [2][128][72]
    __half* Bs = hsh + 2 * ASTG;        // [2][64][136]

    const int tid  = threadIdx.x;
    const int wid  = tid >> 5;
    const int lane = tid & 31;
    const int g    = lane >> 2;
    const int tig  = lane & 3;
    const int wm   = (wid >> 1) * 32;
    const int wn   = (wid & 1) * 64;
    const int krev = wid & 1;           // odd warps reverse k-step order
    const int bx = blockIdx.x, by = blockIdx.y;

    const __half* Ablk = Am + (size_t)by * 128 * K;
    const __half* Bblk = Bw + bx * 128;
    const uint32_t sA = smem_u32(As);
    const uint32_t sB = smem_u32(Bs);

    const int aRow  = lane & 15;
    const int aColH = 8 * (lane >> 4);
    const int bK    = (lane & 7) + 8 * ((lane >> 3) & 1);
    const int bN    = 8 * (lane >> 4);

    auto issue = [&](int c, int s) {
        const __half* Ag = Ablk + c * 64;
#pragma unroll
        for (int i = 0; i < 4; i++) {
            const int idx = i * 256 + tid;
            const int row = idx >> 3, c8 = idx & 7;
            cp16(sA + (uint32_t)(s * ASTG + row * 72 + c8 * 8) * 2,
                 Ag + (size_t)row * K + c8 * 8);
        }
        const __half* Bg = Bblk + (size_t)c * 64 * N;
#pragma unroll
        for (int i = 0; i < 4; i++) {
            const int idx = i * 256 + tid;
            const int row = idx >> 4, c8 = idx & 15;
            cp16(sB + (uint32_t)(s * BSTG + row * 136 + c8 * 8) * 2,
                 Bg + (size_t)row * N + c8 * 8);
        }
        asm volatile("cp.async.commit_group;" ::: "memory");
    };

    float acc[2][8][4];
#pragma unroll
    for (int mt = 0; mt < 2; mt++)
#pragma unroll
        for (int nt = 0; nt < 8; nt++)
#pragma unroll
            for (int r = 0; r < 4; r++) acc[mt][nt][r] = 0.0f;

    issue(0, 0);
    for (int c = 0; c < NC; c++) {
        const int s = c & 1;
        if (c + 1 < NC) {
            issue(c + 1, s ^ 1);
            asm volatile("cp.async.wait_group 1;" ::: "memory");
        } else {
            asm volatile("cp.async.wait_group 0;" ::: "memory");
        }
        __syncthreads();

        const uint32_t A0 = sA + (uint32_t)(s * ASTG) * 2;
        const uint32_t B0 = sB + (uint32_t)(s * BSTG) * 2;
#pragma unroll
        for (int kss = 0; kss < 4; kss++) {
            const int ks = krev ? (3 - kss) : kss;
            const int kh = ks * 16;
            uint32_t af[2][4];
#pragma unroll
            for (int mt = 0; mt < 2; mt++)
                ldsm4(af[mt], A0 + (uint32_t)((wm + mt * 16 + aRow) * 72 + kh + aColH) * 2);
            uint32_t bf[8][2];
#pragma unroll
            for (int ntp = 0; ntp < 4; ntp++) {
                uint32_t t4[4];
                ldsm4t(t4, B0 + (uint32_t)((kh + bK) * 136 + wn + ntp * 16 + bN) * 2);
                bf[2 * ntp][0] = t4[0]; bf[2 * ntp][1] = t4[1];
                bf[2 * ntp + 1][0] = t4[2]; bf[2 * ntp + 1][1] = t4[3];
            }
#pragma unroll
            for (int mt = 0; mt < 2; mt++)
#pragma unroll
                for (int nt = 0; nt < 8; nt++)
                    mma_f16(acc[mt][nt], af[mt], bf[nt]);
        }
        __syncthreads();
    }

    // ---- epilogue ----
    const int nb = bx * 128 + wn;
    const int mb = by * 128 + wm;
    if (EPI == 0) {
        const int which = (bx * 128) / 768;
        __half* dst = (which == 0) ? g_qh : (which == 1) ? g_kh : g_vh;
        const int bb = (by * 128) >> 10;
#pragma unroll
        for (int nt = 0; nt < 8; nt++) {
            const int n  = nb + nt * 8 + 2 * tig;
            const int nc = n - which * 768;
            const int hh = nc >> 6, dd = nc & 63;
            const float bv0 = bias[n], bv1 = bias[n + 1];
            const size_t hbase = (((size_t)(bb * 12 + hh)) << 10);
#pragma unroll
            for (int mt = 0; mt < 2; mt++) {
#pragma unroll
                for (int hr = 0; hr < 2; hr++) {
                    const int m = mb + mt * 16 + g + hr * 8;
                    const int t = m & 1023;
                    float v0 = acc[mt][nt][hr * 2 + 0] + bv0;
                    float v1 = acc[mt][nt][hr * 2 + 1] + bv1;
                    if (which == 0) { v0 *= 0.125f; v1 *= 0.125f; }
                    else if (which == 1 && t > 0) {
                        v0 += rel[(size_t)(t - 1) * 64 + dd];
                        v1 += rel[(size_t)(t - 1) * 64 + dd + 1];
                    }
                    *(__half2*)&dst[(hbase + t) * 64 + dd] = __floats2half2_rn(v0, v1);
                }
            }
        }
    } else {
#pragma unroll
        for (int nt = 0; nt < 8; nt++) {
            const int n = nb + nt * 8 + 2 * tig;
            const float bv0 = bias[n], bv1 = bias[n + 1];
#pragma unroll
            for (int mt = 0; mt < 2; mt++) {
#pragma unroll
                for (int hr = 0; hr < 2; hr++) {
                    const int m = mb + mt * 16 + g + hr * 8;
                    float2 o;
                    o.x = acc[mt][nt][hr * 2 + 0] + bv0;
                    o.y = acc[mt][nt][hr * 2 + 1] + bv1;
                    *(float2*)&Cout[(size_t)m * 768 + n] = o;
                }
            }
        }
    }
}

// ---------------------------------------------- f16 flash attention --------
// 128 queries/block, 256 thr / 8 warps x 16 rows. 64x64 KV tiles, double buf.
// Fully-masked warp-tiles skipped; odd warps reverse k-steps.
#define KTS 4608   // 64*72 halves per KV tile stage
#define QTS2 9216  // 128*72 halves for Q
__global__ void __launch_bounds__(256) flash_h()
{
    extern __shared__ __half fsh[];
    __half* Qs = fsh;                   // [128][72]
    __half* Ks = fsh + QTS2;            // [2][64][72]
    __half* Vs = fsh + QTS2 + 2 * KTS;  // [2][64][72]
    __half* Ps = fsh + QTS2 + 4 * KTS;  // [8][16][72]

    const int qt  = (int)gridDim.x - 1 - (int)blockIdx.x;   // heavy first
    const int bh  = blockIdx.y;
    const int tid = threadIdx.x;
    const int wid = tid >> 5;
    const int lane = tid & 31;
    const int g   = lane >> 2;
    const int tig = lane & 3;
    const int krev = wid & 1;

    const __half* qp = g_qh + (size_t)bh * 65536;
    const __half* kp = g_kh + (size_t)bh * 65536;
    const __half* vp = g_vh + (size_t)bh * 65536;
    const int q0 = qt * 128;
    const int nkt = 2 * qt + 2;

    const uint32_t sQ = smem_u32(Qs);
    const uint32_t sK = smem_u32(Ks);
    const uint32_t sV = smem_u32(Vs);
    const uint32_t sP = smem_u32(Ps) + (uint32_t)(wid * 16 * 72) * 2;

    const int aRow  = lane & 15;
    const int aColH = 8 * (lane >> 4);
    const int kN    = 8 * ((lane >> 4) & 1) + (lane & 7);
    const int kKg   = 8 * ((lane >> 3) & 1);
    const int vK    = (lane & 7) + 8 * ((lane >> 3) & 1);
    const int vD    = 8 * (lane >> 4);

    auto issueKV = [&](int kt, int s) {
        const __half* kg = kp + (size_t)kt * 4096;
        const __half* vg = vp + (size_t)kt * 4096;
        const uint32_t kd = sK + (uint32_t)(s * KTS) * 2;
        const uint32_t vd = sV + (uint32_t)(s * KTS) * 2;
#pragma unroll
        for (int i = 0; i < 2; i++) {
            const int idx = i * 256 + tid;
            const int row = idx >> 3, c8 = idx & 7;
            const uint32_t so = (uint32_t)(row * 72 + c8 * 8) * 2;
            cp16(kd + so, kg + row * 64 + c8 * 8);
            cp16(vd + so, vg + row * 64 + c8 * 8);
        }
        asm volatile("cp.async.commit_group;" ::: "memory");
    };

    {   // Q tile: 128 rows
        const __half* qg = qp + (size_t)q0 * 64;
#pragma unroll
        for (int i = 0; i < 4; i++) {
            const int idx = i * 256 + tid;
            const int row = idx >> 3, c8 = idx & 7;
            cp16(sQ + (uint32_t)(row * 72 + c8 * 8) * 2, qg + row * 64 + c8 * 8);
        }
    }
    issueKV(0, 0);

    float Oacc[8][4];
#pragma unroll
    for (int d = 0; d < 8; d++)
#pragma unroll
        for (int r = 0; r < 4; r++) Oacc[d][r] = 0.0f;
    float mprev[2] = {-1e30f, -1e30f};
    float lsum[2]  = {0.0f, 0.0f};
    const int wq = wid * 16;

    for (int kt = 0; kt < nkt; kt++) {
        const int s = kt & 1;
        const int k0 = kt * 64;
        if (kt + 1 < nkt) {
            issueKV(kt + 1, s ^ 1);
            asm volatile("cp.async.wait_group 1;" ::: "memory");
        } else {
            asm volatile("cp.async.wait_group 0;" ::: "memory");
        }
        __syncthreads();

        // warp-tile fully masked? (all 16 rows precede this key tile)
        if (k0 <= q0 + wq + 15) {
            // ---- S = Q K^T ----
            float sacc[8][4];
#pragma unroll
            for (int nt = 0; nt < 8; nt++)
#pragma unroll
                for (int r = 0; r < 4; r++) sacc[nt][r] = 0.0f;

            const uint32_t K0 = sK + (uint32_t)(s * KTS) * 2;
#pragma unroll
            for (int kss = 0; kss < 4; kss++) {
                const int ks = krev ? (3 - kss) : kss;
                const int kh = ks * 16;
                uint32_t a[4];
                ldsm4(a, sQ + (uint32_t)((wq + aRow) * 72 + kh + aColH) * 2);
#pragma unroll
                for (int ntp = 0; ntp < 4; ntp++) {
                    uint32_t t4[4];
                    ldsm4(t4, K0 + (uint32_t)((ntp * 16 + kN) * 72 + kh + kKg) * 2);
                    mma_f16(sacc[2 * ntp],     a, t4);
                    mma_f16(sacc[2 * ntp + 1], a, t4 + 2);
                }
            }

            // ---- causal mask (only when this warp-tile straddles diagonal) --
            if (k0 + 64 > q0 + wq) {
#pragma unroll
                for (int nt = 0; nt < 8; nt++)
#pragma unroll
                    for (int e = 0; e < 4; e++) {
                        const int rg = q0 + wq + g + ((e >> 1) << 3);
                        const int cg = k0 + nt * 8 + 2 * tig + (e & 1);
                        if (cg > rg) sacc[nt][e] = -1e30f;
                    }
            }

            // ---- online softmax ----
#pragma unroll
            for (int r = 0; r < 2; r++) {
                float mloc = -1e30f;
#pragma unroll
                for (int nt = 0; nt < 8; nt++)
                    mloc = fmaxf(mloc, fmaxf(sacc[nt][2 * r], sacc[nt][2 * r + 1]));
                mloc = fmaxf(mloc, __shfl_xor_sync(0xffffffffu, mloc, 1));
                mloc = fmaxf(mloc, __shfl_xor_sync(0xffffffffu, mloc, 2));
                const float mnew = fmaxf(mprev[r], mloc);
                const float fac  = __expf(mprev[r] - mnew);
                float ls = 0.0f;
#pragma unroll
                for (int nt = 0; nt < 8; nt++) {
                    float p0 = __expf(sacc[nt][2 * r]     - mnew);
                    float p1 = __expf(sacc[nt][2 * r + 1] - mnew);
                    ls += p0 + p1;
                    *(__half2*)((char*)fsh + ((sP - smem_u32(fsh)) +
                        (uint32_t)((g + r * 8) * 72 + nt * 8 + 2 * tig) * 2)) =
                        __floats2half2_rn(p0, p1);
                }
                ls += __shfl_xor_sync(0xffffffffu, ls, 1);
                ls += __shfl_xor_sync(0xffffffffu, ls, 2);
                lsum[r] = lsum[r] * fac + ls;
                mprev[r] = mnew;
#pragma unroll
                for (int d = 0; d < 8; d++) {
                    Oacc[d][2 * r]     *= fac;
                    Oacc[d][2 * r + 1] *= fac;
                }
            }
            __syncwarp();

            // ---- O += P V ----
            const uint32_t V0 = sV + (uint32_t)(s * KTS) * 2;
#pragma unroll
            for (int kss = 0; kss < 4; kss++) {
                const int kc = krev ? (3 - kss) : kss;
                const int kh = kc * 16;
                uint32_t a[4];
                ldsm4(a, sP + (uint32_t)(aRow * 72 + kh + aColH) * 2);
#pragma unroll
                for (int dtp = 0; dtp < 4; dtp++) {
                    uint32_t t4[4];
                    ldsm4t(t4, V0 + (uint32_t)((kh + vK) * 72 + dtp * 16 + vD) * 2);
                    mma_f16(Oacc[2 * dtp],     a, t4);
                    mma_f16(Oacc[2 * dtp + 1], a, t4 + 2);
                }
            }
        }
        __syncthreads();
    }

    // ---- epilogue: y (f16) = O / l ----
    const int bb = bh / 12;
    const int hh = bh - bb * 12;
#pragma unroll
    for (int r = 0; r < 2; r++) {
        const float inv = 1.0f / lsum[r];
        const int t = q0 + wq + g + r * 8;
        __half* yrow = g_yh + ((size_t)(bb * 1024 + t)) * 768 + hh * 64;
#pragma unroll
        for (int dt = 0; dt < 8; dt++) {
            *(__half2*)&yrow[dt * 8 + 2 * tig] =
                __floats2half2_rn(Oacc[dt][2 * r] * inv, Oacc[dt][2 * r + 1] * inv);
        }
    }
}

// ---------------------------------------------------------------------------
extern "C" void kernel_launch(void* const* d_in, const int* in_sizes, int n_in,
                              void* d_out, int out_size)
{
    const float* x      = (const float*)d_in[0];
    const float* w_attn = (const float*)d_in[1];
    const float* b_attn = (const float*)d_in[2];
    const float* w_proj = (const float*)d_in[3];
    const float* b_proj = (const float*)d_in[4];
    const float* rel    = (const float*)d_in[5];
    float* out = (float*)d_out;
    (void)in_sizes; (void)n_in; (void)out_size;

    __half *xh, *wh1, *wh2, *yh;
    cudaGetSymbolAddress((void**)&xh,  g_xh);
    cudaGetSymbolAddress((void**)&wh1, g_wh1);
    cudaGetSymbolAddress((void**)&wh2, g_wh2);
    cudaGetSymbolAddress((void**)&yh,  g_yh);

    const int GSMEM = (2 * 128 * 72 + 2 * 64 * 136) * 2;       // 71680 B
    const int FSMEM = (QTS2 + 4 * KTS + 8 * 16 * 72) * 2;      // 73728 B
    cudaFuncSetAttribute(gemm_h<0>, cudaFuncAttributeMaxDynamicSharedMemorySize, GSMEM);
    cudaFuncSetAttribute(gemm_h<1>, cudaFuncAttributeMaxDynamicSharedMemorySize, GSMEM);
    cudaFuncSetAttribute(flash_h,   cudaFuncAttributeMaxDynamicSharedMemorySize, FSMEM);

    const int TOT4 = N4_X + N4_W1 + N4_W2;
    f2h_all<<<(TOT4 + 255) / 256, 256>>>(x, w_attn, w_proj);

    gemm_h<0><<<dim3(18, 64), 256, GSMEM>>>(xh, wh1, b_attn, rel, nullptr, 2304);

    flash_h<<<dim3(8, 96), 256, FSMEM>>>();

    gemm_h<1><<<dim3(6, 64), 256, GSMEM>>>(yh, wh2, b_proj, nullptr, out, 768);
}

// round 13
// speedup vs baseline: 1.0715x; 1.0715x over previous
#include <cuda_runtime.h>
#include <cuda_fp16.h>
#include <cstdint>
#include <cstddef>

// B=8, T=1024, C=768, H=12, d=64 — full f16 storage, f32 accumulation.
//   prep:  fused f32 -> f16 convert of x, w_attn, w_proj (one launch)
//   QKV :  m16n8k16 f16 mma, 256 thr / 8 warps (32x64 warp tiles) -> q/k/v f16
//   attn:  f16 flash, 64-query blocks, P kept in registers (C-frag == A-frag)
//   proj:  same gemm -> out (f32, +bias)

#define ELEMS_BHTD (8 * 12 * 1024 * 64)
#define ELEMS_BTC  (8 * 1024 * 768)
#define N4_X   (ELEMS_BTC / 4)
#define N4_W1  (768 * 2304 / 4)
#define N4_W2  (768 * 768 / 4)

static __device__ __half g_qh[ELEMS_BHTD];
static __device__ __half g_kh[ELEMS_BHTD];
static __device__ __half g_vh[ELEMS_BHTD];
static __device__ __half g_yh[ELEMS_BTC];
static __device__ __half g_xh[ELEMS_BTC];
static __device__ __half g_wh1[768 * 2304];
static __device__ __half g_wh2[768 * 768];

// ---------------------------------------------------------------- helpers --
__device__ __forceinline__ uint32_t smem_u32(const void* p) {
    uint32_t a;
    asm("{ .reg .u64 t; cvta.to.shared.u64 t, %1; cvt.u32.u64 %0, t; }"
        : "=r"(a) : "l"(p));
    return a;
}
__device__ __forceinline__ void cp16(uint32_t s, const void* g) {
    asm volatile("cp.async.ca.shared.global [%0], [%1], 16;"
                 :: "r"(s), "l"(g) : "memory");
}
__device__ __forceinline__ void ldsm4(uint32_t* r, uint32_t a) {
    asm volatile("ldmatrix.sync.aligned.m8n8.x4.shared.b16 {%0,%1,%2,%3}, [%4];"
                 : "=r"(r[0]), "=r"(r[1]), "=r"(r[2]), "=r"(r[3]) : "r"(a));
}
__device__ __forceinline__ void ldsm4t(uint32_t* r, uint32_t a) {
    asm volatile("ldmatrix.sync.aligned.m8n8.x4.trans.shared.b16 {%0,%1,%2,%3}, [%4];"
                 : "=r"(r[0]), "=r"(r[1]), "=r"(r[2]), "=r"(r[3]) : "r"(a));
}
__device__ __forceinline__ void mma_f16(float* c, const uint32_t* a, const uint32_t* b) {
    asm volatile(
        "mma.sync.aligned.m16n8k16.row.col.f32.f16.f16.f32 "
        "{%0,%1,%2,%3}, {%4,%5,%6,%7}, {%8,%9}, {%0,%1,%2,%3};"
        : "+f"(c[0]), "+f"(c[1]), "+f"(c[2]), "+f"(c[3])
        : "r"(a[0]), "r"(a[1]), "r"(a[2]), "r"(a[3]), "r"(b[0]), "r"(b[1]));
}
__device__ __forceinline__ uint32_t pack_h2(float lo, float hi) {
    __half2 h = __floats2half2_rn(lo, hi);
    return *(uint32_t*)&h;
}

// ----------------------------------------------------------- fused prep ----
__global__ void __launch_bounds__(256) f2h_all(const float* __restrict__ x,
                                               const float* __restrict__ w1,
                                               const float* __restrict__ w2) {
    int i = blockIdx.x * 256 + threadIdx.x;
    const float* in;
    __half* out;
    if (i < N4_X)                { in = x;  out = g_xh; }
    else if (i < N4_X + N4_W1)   { in = w1; out = g_wh1; i -= N4_X; }
    else if (i < N4_X + N4_W1 + N4_W2) { in = w2; out = g_wh2; i -= N4_X + N4_W1; }
    else return;
    float4 v = ((const float4*)in)[i];
    __half2 h0 = __floats2half2_rn(v.x, v.y);
    __half2 h1 = __floats2half2_rn(v.z, v.w);
    uint2 u;
    u.x = *(uint32_t*)&h0;
    u.y = *(uint32_t*)&h1;
    ((uint2*)out)[i] = u;
}

// ------------------------------------------------------------- f16 GEMM ----
// C[m,n] = A[m,:] . Bw[:,n] (+bias). 128x128 block tile, 256 thr / 8 warps,
// warp tile 32x64 (warp grid 4 rows x 2 cols), BK=64 double-buffered cp.async.
template <int EPI>
__global__ void __launch_bounds__(256, 2) gemm_h(
    const __half* __restrict__ Am, const __half* __restrict__ Bw,
    const float* __restrict__ bias, const float* __restrict__ rel,
    float* __restrict__ Cout, const int N)
{
    constexpr int K = 768;
    constexpr int NC = K / 64;
    constexpr int ASTG = 128 * 72;
    constexpr int BSTG = 64 * 136;

    extern __shared__ __half hsh[];
    __half* As = hsh;                   // [2][128][72]
    __half* Bs = hsh + 2 * ASTG;        // [2][64][136]

    const int tid  = threadIdx.x;
    const int wid  = tid >> 5;
    const int lane = tid & 31;
    const int g    = lane >> 2;
    const int tig  = lane & 3;
    const int wm   = (wid >> 1) * 32;
    const int wn   = (wid & 1) * 64;
    const int bx = blockIdx.x, by = blockIdx.y;

    const __half* Ablk = Am + (size_t)by * 128 * K;
    const __half* Bblk = Bw + bx * 128;
    const uint32_t sA = smem_u32(As);
    const uint32_t sB = smem_u32(Bs);

    const int aRow  = lane & 15;
    const int aColH = 8 * (lane >> 4);
    const int bK    = (lane & 7) + 8 * ((lane >> 3) & 1);
    const int bN    = 8 * (lane >> 4);

    auto issue = [&](int c, int s) {
        const __half* Ag = Ablk + c * 64;
#pragma unroll
        for (int i = 0; i < 4; i++) {
            const int idx = i * 256 + tid;
            const int row = idx >> 3, c8 = idx & 7;
            cp16(sA + (uint32_t)(s * ASTG + row * 72 + c8 * 8) * 2,
                 Ag + (size_t)row * K + c8 * 8);
        }
        const __half* Bg = Bblk + (size_t)c * 64 * N;
#pragma unroll
        for (int i = 0; i < 4; i++) {
            const int idx = i * 256 + tid;
            const int row = idx >> 4, c8 = idx & 15;
            cp16(sB + (uint32_t)(s * BSTG + row * 136 + c8 * 8) * 2,
                 Bg + (size_t)row * N + c8 * 8);
        }
        asm volatile("cp.async.commit_group;" ::: "memory");
    };

    float acc[2][8][4];
#pragma unroll
    for (int mt = 0; mt < 2; mt++)
#pragma unroll
        for (int nt = 0; nt < 8; nt++)
#pragma unroll
            for (int r = 0; r < 4; r++) acc[mt][nt][r] = 0.0f;

    issue(0, 0);
    for (int c = 0; c < NC; c++) {
        const int s = c & 1;
        if (c + 1 < NC) {
            issue(c + 1, s ^ 1);
            asm volatile("cp.async.wait_group 1;" ::: "memory");
        } else {
            asm volatile("cp.async.wait_group 0;" ::: "memory");
        }
        __syncthreads();

        const uint32_t A0 = sA + (uint32_t)(s * ASTG) * 2;
        const uint32_t B0 = sB + (uint32_t)(s * BSTG) * 2;
#pragma unroll
        for (int ks = 0; ks < 4; ks++) {
            const int kh = ks * 16;
            uint32_t af[2][4];
#pragma unroll
            for (int mt = 0; mt < 2; mt++)
                ldsm4(af[mt], A0 + (uint32_t)((wm + mt * 16 + aRow) * 72 + kh + aColH) * 2);
            uint32_t bf[8][2];
#pragma unroll
            for (int ntp = 0; ntp < 4; ntp++) {
                uint32_t t4[4];
                ldsm4t(t4, B0 + (uint32_t)((kh + bK) * 136 + wn + ntp * 16 + bN) * 2);
                bf[2 * ntp][0] = t4[0]; bf[2 * ntp][1] = t4[1];
                bf[2 * ntp + 1][0] = t4[2]; bf[2 * ntp + 1][1] = t4[3];
            }
#pragma unroll
            for (int mt = 0; mt < 2; mt++)
#pragma unroll
                for (int nt = 0; nt < 8; nt++)
                    mma_f16(acc[mt][nt], af[mt], bf[nt]);
        }
        __syncthreads();
    }

    // ---- epilogue ----
    const int nb = bx * 128 + wn;
    const int mb = by * 128 + wm;
    if (EPI == 0) {
        const int which = (bx * 128) / 768;
        __half* dst = (which == 0) ? g_qh : (which == 1) ? g_kh : g_vh;
        const int bb = (by * 128) >> 10;
#pragma unroll
        for (int nt = 0; nt < 8; nt++) {
            const int n  = nb + nt * 8 + 2 * tig;
            const int nc = n - which * 768;
            const int hh = nc >> 6, dd = nc & 63;
            const float bv0 = bias[n], bv1 = bias[n + 1];
            const size_t hbase = (((size_t)(bb * 12 + hh)) << 10);
#pragma unroll
            for (int mt = 0; mt < 2; mt++) {
#pragma unroll
                for (int hr = 0; hr < 2; hr++) {
                    const int m = mb + mt * 16 + g + hr * 8;
                    const int t = m & 1023;
                    float v0 = acc[mt][nt][hr * 2 + 0] + bv0;
                    float v1 = acc[mt][nt][hr * 2 + 1] + bv1;
                    if (which == 0) { v0 *= 0.125f; v1 *= 0.125f; }
                    else if (which == 1 && t > 0) {
                        v0 += rel[(size_t)(t - 1) * 64 + dd];
                        v1 += rel[(size_t)(t - 1) * 64 + dd + 1];
                    }
                    *(__half2*)&dst[(hbase + t) * 64 + dd] = __floats2half2_rn(v0, v1);
                }
            }
        }
    } else {
#pragma unroll
        for (int nt = 0; nt < 8; nt++) {
            const int n = nb + nt * 8 + 2 * tig;
            const float bv0 = bias[n], bv1 = bias[n + 1];
#pragma unroll
            for (int mt = 0; mt < 2; mt++) {
#pragma unroll
                for (int hr = 0; hr < 2; hr++) {
                    const int m = mb + mt * 16 + g + hr * 8;
                    float2 o;
                    o.x = acc[mt][nt][hr * 2 + 0] + bv0;
                    o.y = acc[mt][nt][hr * 2 + 1] + bv1;
                    *(float2*)&Cout[(size_t)m * 768 + n] = o;
                }
            }
        }
    }
}

// ---------------------------------------------- f16 flash attention --------
// 64 queries/block, 128 thr / 4 warps x 16 rows. 64x64 KV tiles double-buffered.
// P never touches smem: S C-fragments are repacked in registers as PV A-frags.
#define KTS 4608   // 64*72 halves per tile
__global__ void __launch_bounds__(128, 4) flash_h()
{
    extern __shared__ __half fsh[];
    __half* Qs = fsh;                  // [64][72]
    __half* Ks = fsh + KTS;            // [2][64][72]
    __half* Vs = fsh + 3 * KTS;        // [2][64][72]

    const int qt  = (int)gridDim.x - 1 - (int)blockIdx.x;   // heavy first
    const int bh  = blockIdx.y;
    const int tid = threadIdx.x;
    const int wid = tid >> 5;
    const int lane = tid & 31;
    const int g   = lane >> 2;
    const int tig = lane & 3;

    const __half* qp = g_qh + (size_t)bh * 65536;
    const __half* kp = g_kh + (size_t)bh * 65536;
    const __half* vp = g_vh + (size_t)bh * 65536;
    const int q0 = qt * 64;

    const uint32_t sQ = smem_u32(Qs);
    const uint32_t sK = smem_u32(Ks);
    const uint32_t sV = smem_u32(Vs);

    const int aRow  = lane & 15;
    const int aColH = 8 * (lane >> 4);
    const int kN    = 8 * ((lane >> 4) & 1) + (lane & 7);
    const int kKg   = 8 * ((lane >> 3) & 1);
    const int vK    = (lane & 7) + 8 * ((lane >> 3) & 1);
    const int vD    = 8 * (lane >> 4);

    auto issueKV = [&](int kt, int s) {
        const __half* kg = kp + (size_t)kt * 4096;
        const __half* vg = vp + (size_t)kt * 4096;
        const uint32_t kd = sK + (uint32_t)(s * KTS) * 2;
        const uint32_t vd = sV + (uint32_t)(s * KTS) * 2;
#pragma unroll
        for (int i = 0; i < 4; i++) {
            const int idx = i * 128 + tid;
            const int row = idx >> 3, c8 = idx & 7;
            const uint32_t so = (uint32_t)(row * 72 + c8 * 8) * 2;
            cp16(kd + so, kg + row * 64 + c8 * 8);
            cp16(vd + so, vg + row * 64 + c8 * 8);
        }
        asm volatile("cp.async.commit_group;" ::: "memory");
    };

    {
        const __half* qg = qp + (size_t)q0 * 64;
#pragma unroll
        for (int i = 0; i < 4; i++) {
            const int idx = i * 128 + tid;
            const int row = idx >> 3, c8 = idx & 7;
            cp16(sQ + (uint32_t)(row * 72 + c8 * 8) * 2, qg + row * 64 + c8 * 8);
        }
    }
    issueKV(0, 0);

    float Oacc[8][4];
#pragma unroll
    for (int d = 0; d < 8; d++)
#pragma unroll
        for (int r = 0; r < 4; r++) Oacc[d][r] = 0.0f;
    float mprev[2] = {-1e30f, -1e30f};
    float lsum[2]  = {0.0f, 0.0f};
    const int wq = wid * 16;

    for (int kt = 0; kt <= qt; kt++) {
        const int s = kt & 1;
        if (kt < qt) {
            issueKV(kt + 1, s ^ 1);
            asm volatile("cp.async.wait_group 1;" ::: "memory");
        } else {
            asm volatile("cp.async.wait_group 0;" ::: "memory");
        }
        __syncthreads();

        // ---- S = Q K^T ----
        float sacc[8][4];
#pragma unroll
        for (int nt = 0; nt < 8; nt++)
#pragma unroll
            for (int r = 0; r < 4; r++) sacc[nt][r] = 0.0f;

        const uint32_t K0 = sK + (uint32_t)(s * KTS) * 2;
#pragma unroll
        for (int ks = 0; ks < 4; ks++) {
            const int kh = ks * 16;
            uint32_t a[4];
            ldsm4(a, sQ + (uint32_t)((wq + aRow) * 72 + kh + aColH) * 2);
#pragma unroll
            for (int ntp = 0; ntp < 4; ntp++) {
                uint32_t t4[4];
                ldsm4(t4, K0 + (uint32_t)((ntp * 16 + kN) * 72 + kh + kKg) * 2);
                mma_f16(sacc[2 * ntp],     a, t4);
                mma_f16(sacc[2 * ntp + 1], a, t4 + 2);
            }
        }

        // ---- causal mask on diagonal tile ----
        if (kt == qt) {
#pragma unroll
            for (int nt = 0; nt < 8; nt++)
#pragma unroll
                for (int e = 0; e < 4; e++) {
                    const int row = wq + g + ((e >> 1) << 3);
                    const int col = nt * 8 + 2 * tig + (e & 1);
                    if (col > row) sacc[nt][e] = -1e30f;
                }
        }

        // ---- online softmax (exp values written back into sacc) ----
#pragma unroll
        for (int r = 0; r < 2; r++) {
            float mloc = -1e30f;
#pragma unroll
            for (int nt = 0; nt < 8; nt++)
                mloc = fmaxf(mloc, fmaxf(sacc[nt][2 * r], sacc[nt][2 * r + 1]));
            mloc = fmaxf(mloc, __shfl_xor_sync(0xffffffffu, mloc, 1));
            mloc = fmaxf(mloc, __shfl_xor_sync(0xffffffffu, mloc, 2));
            const float mnew = fmaxf(mprev[r], mloc);
            const float fac  = __expf(mprev[r] - mnew);
            float ls = 0.0f;
#pragma unroll
            for (int nt = 0; nt < 8; nt++) {
                float p0 = __expf(sacc[nt][2 * r]     - mnew);
                float p1 = __expf(sacc[nt][2 * r + 1] - mnew);
                sacc[nt][2 * r]     = p0;
                sacc[nt][2 * r + 1] = p1;
                ls += p0 + p1;
            }
            ls += __shfl_xor_sync(0xffffffffu, ls, 1);
            ls += __shfl_xor_sync(0xffffffffu, ls, 2);
            lsum[r] = lsum[r] * fac + ls;
            mprev[r] = mnew;
#pragma unroll
            for (int d = 0; d < 8; d++) {
                Oacc[d][2 * r]     *= fac;
                Oacc[d][2 * r + 1] *= fac;
            }
        }

        // ---- O += P V : P A-fragments built directly from sacc registers ----
        // C-frag (g,2tig),(g,2tig+1),(g+8,2tig),(g+8,2tig+1) == A-frag layout:
        //   Ra0=(g,2tig..+1)  Ra1=(g+8,2tig..+1)  Ra2=(g,2tig+8..)  Ra3=(g+8,..)
        // k-chunk kc (keys 16kc..16kc+15): cols 2tig+16kc -> sacc[2kc],
        //                                  cols 2tig+8+16kc -> sacc[2kc+1].
        const uint32_t V0 = sV + (uint32_t)(s * KTS) * 2;
#pragma unroll
        for (int kc = 0; kc < 4; kc++) {
            uint32_t a[4];
            a[0] = pack_h2(sacc[2 * kc][0],     sacc[2 * kc][1]);
            a[1] = pack_h2(sacc[2 * kc][2],     sacc[2 * kc][3]);
            a[2] = pack_h2(sacc[2 * kc + 1][0], sacc[2 * kc + 1][1]);
            a[3] = pack_h2(sacc[2 * kc + 1][2], sacc[2 * kc + 1][3]);
            const int kh = kc * 16;
#pragma unroll
            for (int dtp = 0; dtp < 4; dtp++) {
                uint32_t t4[4];
                ldsm4t(t4, V0 + (uint32_t)((kh + vK) * 72 + dtp * 16 + vD) * 2);
                mma_f16(Oacc[2 * dtp],     a, t4);
                mma_f16(Oacc[2 * dtp + 1], a, t4 + 2);
            }
        }
        __syncthreads();
    }

    // ---- epilogue: y (f16) = O / l ----
    const int bb = bh / 12;
    const int hh = bh - bb * 12;
#pragma unroll
    for (int r = 0; r < 2; r++) {
        const float inv = 1.0f / lsum[r];
        const int t = q0 + wq + g + r * 8;
        __half* yrow = g_yh + ((size_t)(bb * 1024 + t)) * 768 + hh * 64;
#pragma unroll
        for (int dt = 0; dt < 8; dt++) {
            *(__half2*)&yrow[dt * 8 + 2 * tig] =
                __floats2half2_rn(Oacc[dt][2 * r] * inv, Oacc[dt][2 * r + 1] * inv);
        }
    }
}

// ---------------------------------------------------------------------------
extern "C" void kernel_launch(void* const* d_in, const int* in_sizes, int n_in,
                              void* d_out, int out_size)
{
    const float* x      = (const float*)d_in[0];
    const float* w_attn = (const float*)d_in[1];
    const float* b_attn = (const float*)d_in[2];
    const float* w_proj = (const float*)d_in[3];
    const float* b_proj = (const float*)d_in[4];
    const float* rel    = (const float*)d_in[5];
    float* out = (float*)d_out;
    (void)in_sizes; (void)n_in; (void)out_size;

    __half *xh, *wh1, *wh2, *yh;
    cudaGetSymbolAddress((void**)&xh,  g_xh);
    cudaGetSymbolAddress((void**)&wh1, g_wh1);
    cudaGetSymbolAddress((void**)&wh2, g_wh2);
    cudaGetSymbolAddress((void**)&yh,  g_yh);

    const int GSMEM = (2 * 128 * 72 + 2 * 64 * 136) * 2;   // 71680 B
    const int FSMEM = 5 * KTS * 2;                          // 46080 B
    cudaFuncSetAttribute(gemm_h<0>, cudaFuncAttributeMaxDynamicSharedMemorySize, GSMEM);
    cudaFuncSetAttribute(gemm_h<1>, cudaFuncAttributeMaxDynamicSharedMemorySize, GSMEM);
    cudaFuncSetAttribute(flash_h,   cudaFuncAttributeMaxDynamicSharedMemorySize, FSMEM);

    const int TOT4 = N4_X + N4_W1 + N4_W2;
    f2h_all<<<(TOT4 + 255) / 256, 256>>>(x, w_attn, w_proj);

    gemm_h<0><<<dim3(18, 64), 256, GSMEM>>>(xh, wh1, b_attn, rel, nullptr, 2304);

    flash_h<<<dim3(16, 96), 128, FSMEM>>>();

    gemm_h<1><<<dim3(6, 64), 256, GSMEM>>>(yh, wh2, b_proj, nullptr, out, 768);
}